// round 10
// baseline (speedup 1.0000x reference)
#include <cuda_runtime.h>
#include <cuda_bf16.h>

// NonSparsePLIF: v[t] = where(v[t-1]*d + x[t] >= 1.0, 0, v[t-1]*d + x[t])
// x_seq [T=16, 4194304] f32, decay [1] f32.
//
// FINAL — best of 9 measured variants, reproduced three times
// (76.4 / 77.0 / 77.1 us kernel, DRAM 79.1-79.8%, ~6.3 TB/s):
//   1 float4 per thread, block=256, grid=4096 (exact cover, no bounds guard),
//   plain loads, __stcs stores (write-once output: evict-first in L2).
//
// Roofline argument: 512 MB mandatory 1:1 read/write traffic (read-once input,
// write-once f32 output, working set 256 MB >> 126 MB L2, T-scan carried in
// registers). ~6.3 TB/s is the achievable HBM ceiling for this mix. Measured
// flat or worse: 2xMLP, __ldcs, persistent grid-stride, block=128, 2-timestep
// burst batching, 256-bit v8 accesses.

#define T_STEPS 16
#define SPATIAL 4194304            // 16*64*64*64
#define SPATIAL4 (SPATIAL / 4)     // 1048576 float4 per timestep plane
#define THREADS 256
#define BLOCKS (SPATIAL4 / THREADS)  // 4096, exact
#define VTH 1.0f

__global__ __launch_bounds__(THREADS) void plif_kernel(
    const float4* __restrict__ x,      // [T, SPATIAL4]
    const float* __restrict__ decay,   // [1]
    float4* __restrict__ out)          // [T, SPATIAL4]
{
    const int i = blockIdx.x * THREADS + threadIdx.x;  // always < SPATIAL4

    const float d = decay[0];

    float4 v = make_float4(0.f, 0.f, 0.f, 0.f);

#pragma unroll
    for (int t = 0; t < T_STEPS; ++t) {
        const size_t idx = (size_t)t * SPATIAL4 + i;
        const float4 xt = x[idx];
        v.x = fmaf(v.x, d, xt.x);
        v.y = fmaf(v.y, d, xt.y);
        v.z = fmaf(v.z, d, xt.z);
        v.w = fmaf(v.w, d, xt.w);
        v.x = (v.x >= VTH) ? 0.f : v.x;
        v.y = (v.y >= VTH) ? 0.f : v.y;
        v.z = (v.z >= VTH) ? 0.f : v.z;
        v.w = (v.w >= VTH) ? 0.f : v.w;
        __stcs(&out[idx], v);
    }
}

extern "C" void kernel_launch(void* const* d_in, const int* in_sizes, int n_in,
                              void* d_out, int out_size)
{
    const float4* x   = (const float4*)d_in[0];
    const float*  dec = (const float*)d_in[1];
    float4*       out = (float4*)d_out;

    plif_kernel<<<BLOCKS, THREADS>>>(x, dec, out);
}

// round 11
// speedup vs baseline: 1.0008x; 1.0008x over previous
#include <cuda_runtime.h>
#include <cuda_bf16.h>

// NonSparsePLIF: v[t] = where(v[t-1]*d + x[t] >= 1.0, 0, v[t-1]*d + x[t])
// x_seq [T=16, 4194304] f32, decay [1] f32. HBM-bound streaming scan.
// R11: best shape (1 float4/thread, block=256, grid=4096 exact) with __stwt
// write-through stores — avoid L2 write-allocate entirely, freeing LTS
// capacity for the read stream. Single-variable change vs the 4x-reproduced
// __stcs baseline (77.0-77.1us, DRAM 79.1-79.8%).

#define T_STEPS 16
#define SPATIAL 4194304            // 16*64*64*64
#define SPATIAL4 (SPATIAL / 4)     // 1048576 float4 per timestep plane
#define THREADS 256
#define BLOCKS (SPATIAL4 / THREADS)  // 4096, exact
#define VTH 1.0f

__global__ __launch_bounds__(THREADS) void plif_kernel(
    const float4* __restrict__ x,      // [T, SPATIAL4]
    const float* __restrict__ decay,   // [1]
    float4* __restrict__ out)          // [T, SPATIAL4]
{
    const int i = blockIdx.x * THREADS + threadIdx.x;  // always < SPATIAL4

    const float d = decay[0];

    float4 v = make_float4(0.f, 0.f, 0.f, 0.f);

#pragma unroll
    for (int t = 0; t < T_STEPS; ++t) {
        const size_t idx = (size_t)t * SPATIAL4 + i;
        const float4 xt = x[idx];
        v.x = fmaf(v.x, d, xt.x);
        v.y = fmaf(v.y, d, xt.y);
        v.z = fmaf(v.z, d, xt.z);
        v.w = fmaf(v.w, d, xt.w);
        v.x = (v.x >= VTH) ? 0.f : v.x;
        v.y = (v.y >= VTH) ? 0.f : v.y;
        v.z = (v.z >= VTH) ? 0.f : v.z;
        v.w = (v.w >= VTH) ? 0.f : v.w;
        __stwt(&out[idx], v);   // write-through: no L2 allocate for write stream
    }
}

extern "C" void kernel_launch(void* const* d_in, const int* in_sizes, int n_in,
                              void* d_out, int out_size)
{
    const float4* x   = (const float4*)d_in[0];
    const float*  dec = (const float*)d_in[1];
    float4*       out = (float4*)d_out;

    plif_kernel<<<BLOCKS, THREADS>>>(x, dec, out);
}